// round 4
// baseline (speedup 1.0000x reference)
#include <cuda_runtime.h>

// ChannelPruner: out[b,o,h,w] = sum_c w[o,c] * x[b,c,h,w]
// x: (32, 256, 56, 56) fp32, w: (256, 256) fp32 (sparse at runtime).
// One block per (o, batch-group-of-4). Compacts W row o once, then streams
// four 12.5 KB planes with 4-way float4 batched loads; batch iterations are
// independent so the scheduler can keep ~8 LDG.128 in flight per thread.

#define N_C 256
#define HW4 784            // 56*56 / 4 (float4 per plane)
#define N_B 32
#define B_GRP 4            // batches per block

__global__ void __launch_bounds__(256) pruner_fused(const float4* __restrict__ x,
                                                    const float*  __restrict__ w,
                                                    float4* __restrict__ out) {
    const int blk = blockIdx.x;            // g * 256 + o
    const int o   = blk & (N_C - 1);
    const int g   = blk >> 8;              // batch group: batches [4g, 4g+4)
    const int tid = threadIdx.x;

    __shared__ int   s_cnt;
    __shared__ int   s_idx[N_C];
    __shared__ float s_val[N_C];

    if (tid == 0) s_cnt = 0;
    __syncthreads();

    // Compact row o of W (order-irrelevant append).
    {
        const float v = __ldg(w + o * N_C + tid);
        if (v != 0.0f) {
            const int pos = atomicAdd(&s_cnt, 1);
            s_idx[pos] = tid;
            s_val[pos] = v;
        }
    }
    __syncthreads();
    const int nnz = s_cnt;

    const bool has3 = (tid < HW4 - 768);   // 16 threads carry the tail position

#pragma unroll 2
    for (int bb = 0; bb < B_GRP; ++bb) {
        const int b = g * B_GRP + bb;
        const float4* __restrict__ xb   = x   + (size_t)b * N_C * HW4;
        float4*       __restrict__ orow = out + ((size_t)b * N_C + o) * HW4;

        float4 a0 = make_float4(0.f, 0.f, 0.f, 0.f);
        float4 a1 = a0, a2 = a0, a3 = a0;

        for (int j = 0; j < nnz; ++j) {
            const float4* __restrict__ p = xb + (size_t)s_idx[j] * HW4 + tid;
            const float v = s_val[j];
            // Independent loads first (MLP = 4 within a batch, 8 across
            // the unrolled pair of batch iterations).
            const float4 v0 = p[0];
            const float4 v1 = p[256];
            const float4 v2 = p[512];
            float4 v3;
            if (has3) v3 = p[768];
            a0.x += v * v0.x; a0.y += v * v0.y; a0.z += v * v0.z; a0.w += v * v0.w;
            a1.x += v * v1.x; a1.y += v * v1.y; a1.z += v * v1.z; a1.w += v * v1.w;
            a2.x += v * v2.x; a2.y += v * v2.y; a2.z += v * v2.z; a2.w += v * v2.w;
            if (has3) {
                a3.x += v * v3.x; a3.y += v * v3.y; a3.z += v * v3.z; a3.w += v * v3.w;
            }
        }

        __stcs(orow + tid,       a0);
        __stcs(orow + tid + 256, a1);
        __stcs(orow + tid + 512, a2);
        if (has3) __stcs(orow + tid + 768, a3);
    }
}

extern "C" void kernel_launch(void* const* d_in, const int* in_sizes, int n_in,
                              void* d_out, int out_size) {
    const float* x = (const float*)d_in[0];   // (32, 256, 56, 56)
    const float* w = (const float*)d_in[1];   // (256, 256, 1, 1)
    float* out = (float*)d_out;               // (32, 256, 56, 56)

    pruner_fused<<<(N_B / B_GRP) * N_C, 256>>>((const float4*)x, w, (float4*)out);
}

// round 5
// speedup vs baseline: 1.0127x; 1.0127x over previous
#include <cuda_runtime.h>

// ChannelPruner: out[b,o,h,w] = sum_c w[o,c] * x[b,c,h,w]
// x: (32, 256, 56, 56) fp32, w: (256, 256) fp32 (sparse at runtime).
// One block per (b, o) plane. Runtime-compacts W row o in smem, then
// dispatches on nnz: 0 -> zero-fill, 1 -> scaled copy (no accumulators,
// minimal registers, MLP=4), >=2 -> general accumulate fallback.

#define N_C 256
#define HW4 784            // 56*56 / 4 (float4 per plane)
#define N_B 32

__global__ void __launch_bounds__(256, 6) pruner_fused(const float4* __restrict__ x,
                                                       const float*  __restrict__ w,
                                                       float4* __restrict__ out) {
    const int bo  = blockIdx.x;           // b * 256 + o
    const int o   = bo & (N_C - 1);
    const int b   = bo >> 8;
    const int tid = threadIdx.x;

    __shared__ int   s_cnt;
    __shared__ int   s_idx[N_C];
    __shared__ float s_val[N_C];

    if (tid == 0) s_cnt = 0;
    __syncthreads();

    // Compact row o of W (order-irrelevant append).
    {
        const float v = __ldg(w + o * N_C + tid);
        if (v != 0.0f) {
            const int pos = atomicAdd(&s_cnt, 1);
            s_idx[pos] = tid;
            s_val[pos] = v;
        }
    }
    __syncthreads();
    const int nnz = s_cnt;

    float4* __restrict__ orow = out + (size_t)bo * HW4;
    const bool has3 = (tid < HW4 - 768);   // 16 threads carry the tail position

    if (nnz == 0) {
        const float4 z = make_float4(0.f, 0.f, 0.f, 0.f);
        __stcs(orow + tid,       z);
        __stcs(orow + tid + 256, z);
        __stcs(orow + tid + 512, z);
        if (has3) __stcs(orow + tid + 768, z);
        return;
    }

    const float4* __restrict__ xb = x + (size_t)b * N_C * HW4;

    if (nnz == 1) {
        // Scaled plane copy: no accumulators, loads are the only live float4s.
        const float  v = s_val[0];
        const float4* __restrict__ p = xb + (size_t)s_idx[0] * HW4 + tid;
        float4 v0 = p[0];
        float4 v1 = p[256];
        float4 v2 = p[512];
        float4 v3;
        if (has3) v3 = p[768];
        v0.x *= v; v0.y *= v; v0.z *= v; v0.w *= v;
        v1.x *= v; v1.y *= v; v1.z *= v; v1.w *= v;
        v2.x *= v; v2.y *= v; v2.z *= v; v2.w *= v;
        __stcs(orow + tid,       v0);
        __stcs(orow + tid + 256, v1);
        __stcs(orow + tid + 512, v2);
        if (has3) {
            v3.x *= v; v3.y *= v; v3.z *= v; v3.w *= v;
            __stcs(orow + tid + 768, v3);
        }
        return;
    }

    // General path (nnz >= 2): one position batch at a time, single acc.
    for (int i = tid; i < HW4; i += 256) {
        float4 acc = make_float4(0.f, 0.f, 0.f, 0.f);
        for (int j = 0; j < nnz; ++j) {
            const float  v  = s_val[j];
            const float4 xv = xb[(size_t)s_idx[j] * HW4 + i];
            acc.x += v * xv.x; acc.y += v * xv.y;
            acc.z += v * xv.z; acc.w += v * xv.w;
        }
        __stcs(orow + i, acc);
    }
}

extern "C" void kernel_launch(void* const* d_in, const int* in_sizes, int n_in,
                              void* d_out, int out_size) {
    const float* x = (const float*)d_in[0];   // (32, 256, 56, 56)
    const float* w = (const float*)d_in[1];   // (256, 256, 1, 1)
    float* out = (float*)d_out;               // (32, 256, 56, 56)

    pruner_fused<<<N_B * N_C, 256>>>((const float4*)x, w, (float4*)out);
}

// round 8
// speedup vs baseline: 1.0136x; 1.0010x over previous
#include <cuda_runtime.h>
#include <cstdint>

// ChannelPruner: out[b,o,h,w] = sum_c w[o,c] * x[b,c,h,w]
// x: (32, 256, 56, 56) fp32, w: (256, 256) fp32 (sparse at runtime).
// One block per (b, o) plane. Runtime-compacts W row o, then dispatches:
//   nnz==0            -> zero-fill
//   nnz==1 && v==1.0  -> async bulk copy G->SMEM->G (bulk engine, no LDG/STG)
//   nnz==1 && v!=1.0  -> bulk load G->SMEM, scale from SMEM, STG
//   nnz>=2            -> general global accumulate loop
// All paths are runtime-dispatched, so any W is handled correctly.

#define N_C 256
#define HW  3136
#define HW4 784
#define N_B 32
#define PLANE_BYTES 12544   // 3136 * 4

__device__ __forceinline__ uint32_t smem_u32(const void* p) {
    return (uint32_t)__cvta_generic_to_shared(p);
}

__device__ __forceinline__ void mbar_init(uint32_t bar) {
    asm volatile("mbarrier.init.shared.b64 [%0], 1;" :: "r"(bar) : "memory");
}

__device__ __forceinline__ void mbar_expect_tx(uint32_t bar, uint32_t bytes) {
    asm volatile("mbarrier.arrive.expect_tx.shared.b64 _, [%0], %1;"
                 :: "r"(bar), "r"(bytes) : "memory");
}

__device__ __forceinline__ void bulk_load_g2s(uint32_t dst, const void* src,
                                              uint32_t bytes, uint32_t bar) {
    asm volatile(
        "cp.async.bulk.shared::cta.global.mbarrier::complete_tx::bytes "
        "[%0], [%1], %2, [%3];"
        :: "r"(dst), "l"(src), "r"(bytes), "r"(bar) : "memory");
}

__device__ __forceinline__ void bulk_store_s2g(void* dst, uint32_t src, uint32_t bytes) {
    asm volatile(
        "cp.async.bulk.global.shared::cta.bulk_group [%0], [%1], %2;"
        :: "l"(dst), "r"(src), "r"(bytes) : "memory");
    asm volatile("cp.async.bulk.commit_group;" ::: "memory");
}

__device__ __forceinline__ void bulk_store_wait_all() {
    asm volatile("cp.async.bulk.wait_group 0;" ::: "memory");
}

__device__ __forceinline__ void fence_async_shared() {
    asm volatile("fence.proxy.async.shared::cta;" ::: "memory");
}

// Canonical acquire try_wait loop (matches ptx_helpers MBARRIER_WAIT_PARITY).
__device__ __forceinline__ void mbar_wait(uint32_t bar, uint32_t parity) {
    asm volatile(
        "{\n\t"
        ".reg .pred P;\n\t"
        "WAIT_%=: \n\t"
        "mbarrier.try_wait.parity.acquire.cta.shared::cta.b64 P, [%0], %1, 0x989680;\n\t"
        "@!P bra WAIT_%=;\n\t"
        "}"
        :: "r"(bar), "r"(parity) : "memory");
}

__global__ void __launch_bounds__(256, 8) pruner_tma(const float* __restrict__ x,
                                                     const float* __restrict__ w,
                                                     float* __restrict__ out) {
    __shared__ int   s_cnt;
    __shared__ int   s_idx[N_C];
    __shared__ float s_val[N_C];
    __shared__ alignas(16)  unsigned long long s_bar;
    __shared__ alignas(128) float s_plane[HW];

    const int bo  = blockIdx.x;          // b * 256 + o
    const int o   = bo & (N_C - 1);
    const int b   = bo >> 8;
    const int tid = threadIdx.x;

    if (tid == 0) {
        s_cnt = 0;
        mbar_init(smem_u32(&s_bar));
    }
    __syncthreads();

    // Compact row o of W (order-irrelevant append).
    {
        const float v = __ldg(w + o * N_C + tid);
        if (v != 0.0f) {
            const int pos = atomicAdd(&s_cnt, 1);
            s_idx[pos] = tid;
            s_val[pos] = v;
        }
    }
    __syncthreads();
    const int nnz = s_cnt;

    float*  orow  = out + (size_t)bo * HW;
    float4* orow4 = (float4*)orow;
    const bool has3 = (tid < HW4 - 768);

    if (nnz == 0) {
        const float4 z = make_float4(0.f, 0.f, 0.f, 0.f);
        __stcs(orow4 + tid,       z);
        __stcs(orow4 + tid + 256, z);
        __stcs(orow4 + tid + 512, z);
        if (has3) __stcs(orow4 + tid + 768, z);
        return;
    }

    if (nnz == 1) {
        const float  v      = s_val[0];
        const float* xplane = x + ((size_t)b * N_C + s_idx[0]) * HW;
        const uint32_t bar  = smem_u32(&s_bar);
        const uint32_t sdst = smem_u32(s_plane);

        if (tid == 0) {
            mbar_expect_tx(bar, PLANE_BYTES);
            bulk_load_g2s(sdst, xplane, PLANE_BYTES, bar);
        }

        if (v == 1.0f) {
            // Pure plane copy: thread 0 bounces SMEM back out via the bulk
            // engine; no per-element work, no register/LSU pressure.
            if (tid == 0) {
                mbar_wait(bar, 0);
                fence_async_shared();
                bulk_store_s2g(orow, sdst, PLANE_BYTES);
                bulk_store_wait_all();
            }
            return;
        }

        // Scaled copy: everyone waits for the plane, scales from SMEM.
        mbar_wait(bar, 0);
        const float4* sp = (const float4*)s_plane;
        float4 v0 = sp[tid];
        float4 v1 = sp[tid + 256];
        float4 v2 = sp[tid + 512];
        float4 v3;
        if (has3) v3 = sp[tid + 768];
        v0.x *= v; v0.y *= v; v0.z *= v; v0.w *= v;
        v1.x *= v; v1.y *= v; v1.z *= v; v1.w *= v;
        v2.x *= v; v2.y *= v; v2.z *= v; v2.w *= v;
        __stcs(orow4 + tid,       v0);
        __stcs(orow4 + tid + 256, v1);
        __stcs(orow4 + tid + 512, v2);
        if (has3) {
            v3.x *= v; v3.y *= v; v3.z *= v; v3.w *= v;
            __stcs(orow4 + tid + 768, v3);
        }
        return;
    }

    // General path (nnz >= 2): accumulate straight from global.
    const float4* xb = (const float4*)(x + (size_t)b * N_C * HW);
    for (int i = tid; i < HW4; i += 256) {
        float4 acc = make_float4(0.f, 0.f, 0.f, 0.f);
        for (int j = 0; j < nnz; ++j) {
            const float  cv = s_val[j];
            const float4 xv = xb[(size_t)s_idx[j] * HW4 + i];
            acc.x += cv * xv.x; acc.y += cv * xv.y;
            acc.z += cv * xv.z; acc.w += cv * xv.w;
        }
        __stcs(orow4 + i, acc);
    }
}

extern "C" void kernel_launch(void* const* d_in, const int* in_sizes, int n_in,
                              void* d_out, int out_size) {
    const float* x = (const float*)d_in[0];   // (32, 256, 56, 56)
    const float* w = (const float*)d_in[1];   // (256, 256, 1, 1)
    float* out = (float*)d_out;               // (32, 256, 56, 56)

    pruner_tma<<<N_B * N_C, 256>>>(x, w, out);
}